// round 1
// baseline (speedup 1.0000x reference)
#include <cuda_runtime.h>
#include <math.h>

#define UNITS 1024
#define BATCH 32
#define SEQ   2048

// Scratch (allocation-free rule: __device__ globals)
__device__ float g_dec2[BATCH * UNITS];   // decoder + W_b + U_b, per batch
__device__ float g_scores[BATCH * SEQ];   // pre-softmax scores

// ---------------------------------------------------------------------------
// Kernel A: dec2[b,h] = sum_u s_prev[b,u] * W_w[u,h] + W_b[h] + U_b[h]
// grid (UNITS/256, BATCH), block 256
// ---------------------------------------------------------------------------
__global__ void decoder_kernel(const float* __restrict__ s_prev,
                               const float* __restrict__ W_w,
                               const float* __restrict__ W_b,
                               const float* __restrict__ U_b) {
    __shared__ float ssp[UNITS];
    int b = blockIdx.y;
    int h = blockIdx.x * 256 + threadIdx.x;
    for (int u = threadIdx.x; u < UNITS; u += 256)
        ssp[u] = s_prev[b * UNITS + u];
    __syncthreads();

    float acc = 0.f;
    #pragma unroll 8
    for (int u = 0; u < UNITS; u++)
        acc = fmaf(ssp[u], W_w[(size_t)u * UNITS + h], acc);
    g_dec2[b * UNITS + h] = acc + W_b[h] + U_b[h];
}

// ---------------------------------------------------------------------------
// Zero the score accumulators (atomicAdd target)
// ---------------------------------------------------------------------------
__global__ void zero_scores_kernel() {
    int i = blockIdx.x * 256 + threadIdx.x;
    if (i < BATCH * SEQ) g_scores[i] = 0.f;
}

// ---------------------------------------------------------------------------
// Kernel B: fused GEMM + tanh + V_w reduction.
//   C[m,n] = sum_k hidden2d[m,k] * U_w[k,n]      (m = b*SEQ + s)
//   score[m] += sum_n tanh(C[m,n] + dec2[b,n]) * V_w[n]
// Tiling: BM=64, BN=64, BK=16, 256 threads, 4x4 microtile per thread.
// Each block atomicAdds its BN-slice partial row-sums into g_scores.
// A 64-row tile never crosses a batch boundary (SEQ % 64 == 0).
// ---------------------------------------------------------------------------
#define BM 64
#define BN 64
#define BK 16

__global__ __launch_bounds__(256) void score_gemm_kernel(
        const float* __restrict__ A,    // hidden (B*S, UNITS)
        const float* __restrict__ Bw,   // U_w (UNITS, UNITS)
        const float* __restrict__ Vw) { // V_w (UNITS)
    __shared__ float As[BK][BM + 4];    // K-major (transposed) A tile
    __shared__ float Bs[BK][BN + 4];
    __shared__ float sred[BM][17];

    const int tid = threadIdx.x;
    const int tx = tid & 15;            // 0..15 -> n microtile
    const int ty = tid >> 4;            // 0..15 -> m microtile
    const int m0 = blockIdx.y * BM;
    const int n0 = blockIdx.x * BN;
    const int bidx = m0 / SEQ;

    // global-load assignments
    const int ar = tid >> 2;            // 0..63: A row in tile
    const int ak = (tid & 3) * 4;       // A k-vec start
    const int bk = tid >> 4;            // 0..15: B k row
    const int bn = (tid & 15) * 4;      // B n-vec start

    float acc[4][4] = {};

    for (int k0 = 0; k0 < UNITS; k0 += BK) {
        float4 av = *(const float4*)&A[(size_t)(m0 + ar) * UNITS + k0 + ak];
        As[ak + 0][ar] = av.x;
        As[ak + 1][ar] = av.y;
        As[ak + 2][ar] = av.z;
        As[ak + 3][ar] = av.w;
        *(float4*)&Bs[bk][bn] =
            *(const float4*)&Bw[(size_t)(k0 + bk) * UNITS + n0 + bn];
        __syncthreads();

        #pragma unroll
        for (int kk = 0; kk < BK; kk++) {
            float4 a = *(float4*)&As[kk][ty * 4];
            float4 b = *(float4*)&Bs[kk][tx * 4];
            acc[0][0] = fmaf(a.x, b.x, acc[0][0]);
            acc[0][1] = fmaf(a.x, b.y, acc[0][1]);
            acc[0][2] = fmaf(a.x, b.z, acc[0][2]);
            acc[0][3] = fmaf(a.x, b.w, acc[0][3]);
            acc[1][0] = fmaf(a.y, b.x, acc[1][0]);
            acc[1][1] = fmaf(a.y, b.y, acc[1][1]);
            acc[1][2] = fmaf(a.y, b.z, acc[1][2]);
            acc[1][3] = fmaf(a.y, b.w, acc[1][3]);
            acc[2][0] = fmaf(a.z, b.x, acc[2][0]);
            acc[2][1] = fmaf(a.z, b.y, acc[2][1]);
            acc[2][2] = fmaf(a.z, b.z, acc[2][2]);
            acc[2][3] = fmaf(a.z, b.w, acc[2][3]);
            acc[3][0] = fmaf(a.w, b.x, acc[3][0]);
            acc[3][1] = fmaf(a.w, b.y, acc[3][1]);
            acc[3][2] = fmaf(a.w, b.z, acc[3][2]);
            acc[3][3] = fmaf(a.w, b.w, acc[3][3]);
        }
        __syncthreads();
    }

    // Epilogue: tanh + dot with V_w slice, per-row partial
    #pragma unroll
    for (int i = 0; i < 4; i++) {
        float p = 0.f;
        #pragma unroll
        for (int j = 0; j < 4; j++) {
            int n = n0 + tx * 4 + j;
            float t = tanhf(acc[i][j] + g_dec2[bidx * UNITS + n]);
            p = fmaf(t, Vw[n], p);
        }
        sred[ty * 4 + i][tx] = p;
    }
    __syncthreads();

    if (tid < BM) {
        float s = 0.f;
        #pragma unroll
        for (int j = 0; j < 16; j++) s += sred[tid][j];
        atomicAdd(&g_scores[m0 + tid], s);
    }
}

// ---------------------------------------------------------------------------
// Kernel C: softmax over S per batch. Writes alpha into out buffer.
// grid BATCH, block 256
// ---------------------------------------------------------------------------
__global__ void softmax_kernel(float* __restrict__ alpha_out) {
    __shared__ float red[256];
    const int b = blockIdx.x;
    const int tid = threadIdx.x;
    const float* sc = g_scores + b * SEQ;
    float* al = alpha_out + b * SEQ;

    float m = -INFINITY;
    for (int s = tid; s < SEQ; s += 256) m = fmaxf(m, sc[s]);
    red[tid] = m;
    __syncthreads();
    for (int o = 128; o > 0; o >>= 1) {
        if (tid < o) red[tid] = fmaxf(red[tid], red[tid + o]);
        __syncthreads();
    }
    m = red[0];
    __syncthreads();

    float sum = 0.f;
    for (int s = tid; s < SEQ; s += 256) {
        float e = expf(sc[s] - m);
        al[s] = e;
        sum += e;
    }
    red[tid] = sum;
    __syncthreads();
    for (int o = 128; o > 0; o >>= 1) {
        if (tid < o) red[tid] += red[tid + o];
        __syncthreads();
    }
    float inv = 1.f / red[0];
    __syncthreads();

    for (int s = tid; s < SEQ; s += 256) al[s] *= inv;
}

// ---------------------------------------------------------------------------
// Kernel D: context[b,u] = sum_s alpha[b,s] * hidden[b,s,u]
// grid (UNITS/256, BATCH), block 256
// ---------------------------------------------------------------------------
__global__ void context_kernel(const float* __restrict__ hidden,
                               const float* __restrict__ alpha,
                               float* __restrict__ ctx_out) {
    __shared__ float sal[SEQ];
    const int b = blockIdx.y;
    const int u = blockIdx.x * 256 + threadIdx.x;
    for (int s = threadIdx.x; s < SEQ; s += 256)
        sal[s] = alpha[b * SEQ + s];
    __syncthreads();

    const float* hp = hidden + (size_t)b * SEQ * UNITS + u;
    float acc = 0.f;
    #pragma unroll 4
    for (int s = 0; s < SEQ; s++)
        acc = fmaf(sal[s], hp[(size_t)s * UNITS], acc);
    ctx_out[b * UNITS + u] = acc;
}

// ---------------------------------------------------------------------------
extern "C" void kernel_launch(void* const* d_in, const int* in_sizes, int n_in,
                              void* d_out, int out_size) {
    const float* s_prev = (const float*)d_in[0];
    const float* hidden = (const float*)d_in[1];
    const float* W_w    = (const float*)d_in[2];
    const float* W_b    = (const float*)d_in[3];
    const float* U_w    = (const float*)d_in[4];
    const float* U_b    = (const float*)d_in[5];
    const float* V_w    = (const float*)d_in[6];
    // V_b (d_in[7]) is softmax-invariant -> intentionally unused.

    float* out_ctx   = (float*)d_out;                   // BATCH*UNITS
    float* out_alpha = (float*)d_out + BATCH * UNITS;   // BATCH*SEQ

    decoder_kernel<<<dim3(UNITS / 256, BATCH), 256>>>(s_prev, W_w, W_b, U_b);
    zero_scores_kernel<<<(BATCH * SEQ + 255) / 256, 256>>>();
    score_gemm_kernel<<<dim3(UNITS / BN, (BATCH * SEQ) / BM), 256>>>(hidden, U_w, V_w);
    softmax_kernel<<<BATCH, 256>>>(out_alpha);
    context_kernel<<<dim3(UNITS / 256, BATCH), 256>>>(hidden, out_alpha, out_ctx);
}

// round 3
// speedup vs baseline: 6.4759x; 6.4759x over previous
#include <cuda_runtime.h>
#include <cuda_fp16.h>
#include <math.h>
#include <stdint.h>

#define UNITS 1024
#define BATCH 32
#define SEQ   2048
#define MTOT  (BATCH * SEQ)     // 65536

// ------------------------- device scratch (no allocs allowed) -------------
__device__ float g_dec2[BATCH * UNITS];                 // W(s_prev)+W_b+U_b
__device__ float g_scores[MTOT];                        // pre-softmax scores
__device__ __align__(1024) __half g_hid16[(size_t)MTOT * UNITS];  // hidden fp16
__device__ __align__(1024) __half g_U16[UNITS * UNITS];           // U_w^T fp16 [n,k]

// ------------------------- helpers ----------------------------------------
__device__ __forceinline__ uint32_t smem_u32(const void* p) {
    uint32_t a;
    asm("{ .reg .u64 t; cvta.to.shared.u64 t, %1; cvt.u32.u64 %0, t; }"
        : "=r"(a) : "l"(p));
    return a;
}
__device__ __forceinline__ float tanh_fast(float x) {
    float y;
    asm("tanh.approx.f32 %0, %1;" : "=f"(y) : "f"(x));
    return y;
}
__device__ __forceinline__ void ldsm_x4(uint32_t (&r)[4], uint32_t addr) {
    asm volatile("ldmatrix.sync.aligned.m8n8.x4.shared.b16 {%0,%1,%2,%3}, [%4];"
                 : "=r"(r[0]), "=r"(r[1]), "=r"(r[2]), "=r"(r[3]) : "r"(addr));
}
__device__ __forceinline__ void mma16816(float (&d)[4], const uint32_t (&a)[4],
                                         uint32_t b0, uint32_t b1) {
    asm volatile(
        "mma.sync.aligned.m16n8k16.row.col.f32.f16.f16.f32 "
        "{%0,%1,%2,%3}, {%4,%5,%6,%7}, {%8,%9}, {%0,%1,%2,%3};"
        : "+f"(d[0]), "+f"(d[1]), "+f"(d[2]), "+f"(d[3])
        : "r"(a[0]), "r"(a[1]), "r"(a[2]), "r"(a[3]), "r"(b0), "r"(b1));
}
#define CP_ASYNC16(dst, src) \
    asm volatile("cp.async.cg.shared.global [%0], [%1], 16;" :: "r"(dst), "l"(src))
#define CP_COMMIT() asm volatile("cp.async.commit_group;" ::: "memory")
#define CP_WAIT1()  asm volatile("cp.async.wait_group 1;" ::: "memory")

// ------------------------- conversion kernels -----------------------------
struct alignas(8) H4 { __half2 a, b; };

__global__ void cvt_hidden_kernel(const float4* __restrict__ in) {
    size_t i = (size_t)blockIdx.x * 256 + threadIdx.x;   // 16M float4s
    float4 v = in[i];
    H4 o;
    o.a = __floats2half2_rn(v.x, v.y);
    o.b = __floats2half2_rn(v.z, v.w);
    ((H4*)g_hid16)[i] = o;
}

__global__ void cvt_U_kernel(const float* __restrict__ U) {
    // g_U16[n*1024 + k] = (half) U[k*1024 + n]
    __shared__ float t[32][33];
    int k0 = blockIdx.x * 32, n0 = blockIdx.y * 32;
    int tx = threadIdx.x, ty = threadIdx.y;
    #pragma unroll
    for (int j = 0; j < 4; j++)
        t[ty + j * 8][tx] = U[(size_t)(k0 + ty + j * 8) * UNITS + n0 + tx];
    __syncthreads();
    #pragma unroll
    for (int j = 0; j < 4; j++)
        g_U16[(size_t)(n0 + ty + j * 8) * UNITS + k0 + tx] =
            __float2half_rn(t[tx][ty + j * 8]);
}

// ------------------------- decoder ----------------------------------------
__global__ void decoder_kernel(const float* __restrict__ s_prev,
                               const float* __restrict__ W_w,
                               const float* __restrict__ W_b,
                               const float* __restrict__ U_b) {
    __shared__ float ssp[UNITS];
    int b = blockIdx.y;
    int h = blockIdx.x * 256 + threadIdx.x;
    for (int u = threadIdx.x; u < UNITS; u += 256)
        ssp[u] = s_prev[b * UNITS + u];
    __syncthreads();
    float acc = 0.f;
    #pragma unroll 8
    for (int u = 0; u < UNITS; u++)
        acc = fmaf(ssp[u], W_w[(size_t)u * UNITS + h], acc);
    g_dec2[b * UNITS + h] = acc + W_b[h] + U_b[h];
}

// ------------------------- zero scratch + out_ctx -------------------------
__global__ void zero_kernel(float* __restrict__ ctx) {
    int i = blockIdx.x * 256 + threadIdx.x;
    if (i < MTOT) g_scores[i] = 0.f;
    if (i < BATCH * UNITS) ctx[i] = 0.f;
}

// ------------------------- fused HMMA score GEMM --------------------------
// C[m,n] = sum_k hid16[m,k] * U16[n,k];  score[m] += sum_n tanh(C+dec)*Vw[n]
// BM=128, BN=128, BK=32, 3-stage cp.async pipeline, 8 warps (2 m x 4 n).
#define BK      32
#define STAGES  3
#define ROWH    40                    // halves per smem row (32 data + 8 pad)
#define TILEH   (128 * ROWH)          // halves per tile (A or B)

__global__ __launch_bounds__(256, 2) void score_gemm_kernel(
        const float* __restrict__ Vw) {
    extern __shared__ __align__(16) char smem[];
    __half* sh = (__half*)smem;
    float* dec_s = (float*)(sh + STAGES * 2 * TILEH);
    float* vw_s  = dec_s + 128;

    const uint32_t sbase = smem_u32(sh);
    const int tid  = threadIdx.x;
    const int wid  = tid >> 5;
    const int lane = tid & 31;
    const int warp_m = wid & 1;       // 0..1  (64-row slabs)
    const int warp_n = wid >> 1;      // 0..3  (32-col slabs)

    const int n0 = blockIdx.x * 128;  // n fast-varying -> A reuse via L2
    const int m0 = blockIdx.y * 128;
    const int bidx = m0 >> 11;        // m0 / SEQ

    if (tid < 128)       dec_s[tid] = g_dec2[bidx * UNITS + n0 + tid];
    else                 vw_s[tid - 128] = Vw[n0 + tid - 128];

    const __half* gA = g_hid16 + (size_t)m0 * UNITS;
    const __half* gB = g_U16   + (size_t)n0 * UNITS;

    // per-thread cp.async assignments: 2 A-chunks + 2 B-chunks per stage
    const int c0r = (tid      ) >> 2, c0k = (tid      ) & 3;
    const int c1r = (tid + 256) >> 2, c1k = (tid + 256) & 3;

    float acc[4][4][4] = {};

    auto load_stage = [&](int s, int k0) {
        uint32_t aOff = sbase + (uint32_t)(s * 2 * TILEH) * 2;
        uint32_t bOff = aOff + (uint32_t)TILEH * 2;
        CP_ASYNC16(aOff + c0r * 80 + c0k * 16, gA + (size_t)c0r * UNITS + k0 + c0k * 8);
        CP_ASYNC16(aOff + c1r * 80 + c1k * 16, gA + (size_t)c1r * UNITS + k0 + c1k * 8);
        CP_ASYNC16(bOff + c0r * 80 + c0k * 16, gB + (size_t)c0r * UNITS + k0 + c0k * 8);
        CP_ASYNC16(bOff + c1r * 80 + c1k * 16, gB + (size_t)c1r * UNITS + k0 + c1k * 8);
    };

    load_stage(0, 0);  CP_COMMIT();
    load_stage(1, BK); CP_COMMIT();

    const int lrow = lane & 15;
    const int lkb  = (lane >> 4) * 16;
    const int bg   = lane >> 3;       // 0..3 ldmatrix group
    const int blg  = lane & 7;

    #pragma unroll 1
    for (int kt = 0; kt < UNITS / BK; kt++) {
        CP_WAIT1();
        __syncthreads();
        if (kt + 2 < UNITS / BK) load_stage((kt + 2) % STAGES, (kt + 2) * BK);
        CP_COMMIT();

        const int s = kt % STAGES;
        const uint32_t aOff = sbase + (uint32_t)(s * 2 * TILEH) * 2;
        const uint32_t bOff = aOff + (uint32_t)TILEH * 2;

        #pragma unroll
        for (int ks = 0; ks < 2; ks++) {
            uint32_t afr[4][4];
            #pragma unroll
            for (int mt = 0; mt < 4; mt++)
                ldsm_x4(afr[mt], aOff + (warp_m * 64 + mt * 16 + lrow) * 80
                                      + ks * 32 + lkb);
            uint32_t bfr[4][2];
            #pragma unroll
            for (int p = 0; p < 2; p++) {
                uint32_t r[4];
                ldsm_x4(r, bOff + (warp_n * 32 + p * 16 + (bg >> 1) * 8 + blg) * 80
                              + ks * 32 + (bg & 1) * 16);
                bfr[2 * p][0]     = r[0]; bfr[2 * p][1]     = r[1];
                bfr[2 * p + 1][0] = r[2]; bfr[2 * p + 1][1] = r[3];
            }
            #pragma unroll
            for (int mt = 0; mt < 4; mt++)
                #pragma unroll
                for (int nt = 0; nt < 4; nt++)
                    mma16816(acc[mt][nt], afr[mt], bfr[nt][0], bfr[nt][1]);
        }
        __syncthreads();
    }

    // ---- fused epilogue: tanh + Vw dot, quad-reduce, atomic row add ----
    float tdec[8], tvw[8];
    #pragma unroll
    for (int nt = 0; nt < 4; nt++)
        #pragma unroll
        for (int j = 0; j < 2; j++) {
            int c = warp_n * 32 + nt * 8 + (lane & 3) * 2 + j;
            tdec[nt * 2 + j] = dec_s[c];
            tvw[nt * 2 + j]  = vw_s[c];
        }

    #pragma unroll
    for (int mt = 0; mt < 4; mt++) {
        float p0 = 0.f, p1 = 0.f;
        #pragma unroll
        for (int nt = 0; nt < 4; nt++) {
            p0 = fmaf(tanh_fast(acc[mt][nt][0] + tdec[nt * 2]),     tvw[nt * 2],     p0);
            p0 = fmaf(tanh_fast(acc[mt][nt][1] + tdec[nt * 2 + 1]), tvw[nt * 2 + 1], p0);
            p1 = fmaf(tanh_fast(acc[mt][nt][2] + tdec[nt * 2]),     tvw[nt * 2],     p1);
            p1 = fmaf(tanh_fast(acc[mt][nt][3] + tdec[nt * 2 + 1]), tvw[nt * 2 + 1], p1);
        }
        p0 += __shfl_xor_sync(0xffffffffu, p0, 1);
        p0 += __shfl_xor_sync(0xffffffffu, p0, 2);
        p1 += __shfl_xor_sync(0xffffffffu, p1, 1);
        p1 += __shfl_xor_sync(0xffffffffu, p1, 2);
        if ((lane & 3) == 0) {
            int r = m0 + warp_m * 64 + mt * 16 + (lane >> 2);
            atomicAdd(&g_scores[r],     p0);
            atomicAdd(&g_scores[r + 8], p1);
        }
    }
}

// ------------------------- softmax ----------------------------------------
__global__ void softmax_kernel(float* __restrict__ alpha_out) {
    __shared__ float red[256];
    const int b = blockIdx.x;
    const int tid = threadIdx.x;
    const float* sc = g_scores + b * SEQ;
    float* al = alpha_out + b * SEQ;

    float m = -INFINITY;
    for (int s = tid; s < SEQ; s += 256) m = fmaxf(m, sc[s]);
    red[tid] = m;
    __syncthreads();
    for (int o = 128; o > 0; o >>= 1) {
        if (tid < o) red[tid] = fmaxf(red[tid], red[tid + o]);
        __syncthreads();
    }
    m = red[0];
    __syncthreads();

    float sum = 0.f;
    for (int s = tid; s < SEQ; s += 256) {
        float e = expf(sc[s] - m);
        al[s] = e;
        sum += e;
    }
    red[tid] = sum;
    __syncthreads();
    for (int o = 128; o > 0; o >>= 1) {
        if (tid < o) red[tid] += red[tid + o];
        __syncthreads();
    }
    float inv = 1.f / red[0];
    __syncthreads();
    for (int s = tid; s < SEQ; s += 256) al[s] *= inv;
}

// ------------------------- context (fp16 hidden, s-split) -----------------
__global__ __launch_bounds__(256) void context16_kernel(
        const float* __restrict__ alpha, float* __restrict__ ctx) {
    __shared__ float sal[512];
    const int b = blockIdx.y;
    const int u2 = blockIdx.x * 256 + threadIdx.x;   // half2 index
    const int s0 = blockIdx.z * 512;
    for (int s = threadIdx.x; s < 512; s += 256)
        sal[s] = alpha[b * SEQ + s0 + s];
    __syncthreads();

    const __half2* hp = (const __half2*)g_hid16 + ((size_t)b * SEQ + s0) * 512 + u2;
    float ax = 0.f, ay = 0.f;
    #pragma unroll 8
    for (int s = 0; s < 512; s++) {
        float2 f = __half22float2(hp[(size_t)s * 512]);
        float a = sal[s];
        ax = fmaf(a, f.x, ax);
        ay = fmaf(a, f.y, ay);
    }
    atomicAdd(&ctx[b * UNITS + u2 * 2],     ax);
    atomicAdd(&ctx[b * UNITS + u2 * 2 + 1], ay);
}

// ------------------------- host launcher ----------------------------------
extern "C" void kernel_launch(void* const* d_in, const int* in_sizes, int n_in,
                              void* d_out, int out_size) {
    const float* s_prev = (const float*)d_in[0];
    const float* hidden = (const float*)d_in[1];
    const float* W_w    = (const float*)d_in[2];
    const float* W_b    = (const float*)d_in[3];
    const float* U_w    = (const float*)d_in[4];
    const float* U_b    = (const float*)d_in[5];
    const float* V_w    = (const float*)d_in[6];
    // d_in[7] = V_b: constant shift of scores, softmax-invariant -> unused.

    float* out_ctx   = (float*)d_out;                  // BATCH*UNITS
    float* out_alpha = (float*)d_out + BATCH * UNITS;  // BATCH*SEQ

    const int smem_bytes = STAGES * 2 * TILEH * 2 + 256 * sizeof(float);
    static int configured = 0;
    cudaFuncSetAttribute(score_gemm_kernel,
                         cudaFuncAttributeMaxDynamicSharedMemorySize, smem_bytes);
    (void)configured;

    // 1. conversions
    cvt_hidden_kernel<<<(MTOT * (UNITS / 4)) / 256, 256>>>((const float4*)hidden);
    cvt_U_kernel<<<dim3(UNITS / 32, UNITS / 32), dim3(32, 8)>>>(U_w);
    // 2. decoder vector + zero scratch
    decoder_kernel<<<dim3(UNITS / 256, BATCH), 256>>>(s_prev, W_w, W_b, U_b);
    zero_kernel<<<(MTOT + 255) / 256, 256>>>(out_ctx);
    // 3. fused HMMA GEMM + tanh + V reduction
    score_gemm_kernel<<<dim3(UNITS / 128, MTOT / 128), 256, smem_bytes>>>(V_w);
    // 4. softmax
    softmax_kernel<<<BATCH, 256>>>(out_alpha);
    // 5. context from fp16 hidden
    context16_kernel<<<dim3(2, BATCH, 4), 256>>>(out_alpha, out_ctx);
}